// round 1
// baseline (speedup 1.0000x reference)
#include <cuda_runtime.h>
#include <math.h>

// Problem constants
#define B_  2
#define L_  2048
#define D_  1024
#define H_  16
#define MT_ (B_ * L_)          // 4096 rows for all projection GEMMs

// Scratch (allocation-free rule: __device__ globals). 4 x 16 MB = 64 MB.
__device__ float g_Q[(size_t)MT_ * D_];
__device__ float g_K[(size_t)MT_ * D_];
__device__ float g_V[(size_t)MT_ * D_];
__device__ float g_C[(size_t)MT_ * D_];

// ---------------------------------------------------------------------------
// GEMM NT: C[M,N] = A[M,K] @ W[N,K]^T   with M=4096, N=K=1024 (fixed).
// 128x128 block tile, BK=8, 256 threads, 8x8 register tile per thread.
// ---------------------------------------------------------------------------
__device__ __forceinline__ void gemm_nt_body(const float* __restrict__ A,
                                             const float* __restrict__ W,
                                             float* __restrict__ C) {
    constexpr int K = 1024, N = 1024;
    __shared__ float As[8][132];   // padded: conflict-free transposed stores
    __shared__ float Bs[8][132];
    const int t  = threadIdx.x;
    const int tx = t & 15, ty = t >> 4;
    const int m0 = blockIdx.x * 128, n0 = blockIdx.y * 128;
    const int lk = t & 7, lm = t >> 3;          // lm in 0..31

    float acc[8][8];
#pragma unroll
    for (int i = 0; i < 8; i++)
#pragma unroll
        for (int j = 0; j < 8; j++) acc[i][j] = 0.f;

    const float* Ap = A + (size_t)(m0 + lm) * K + lk;
    const float* Wp = W + (size_t)(n0 + lm) * K + lk;

    for (int k0 = 0; k0 < K; k0 += 8) {
#pragma unroll
        for (int r = 0; r < 4; r++) {
            As[lk][lm + 32 * r] = Ap[(size_t)(32 * r) * K + k0];
            Bs[lk][lm + 32 * r] = Wp[(size_t)(32 * r) * K + k0];
        }
        __syncthreads();
#pragma unroll
        for (int kk = 0; kk < 8; kk++) {
            float a[8], b[8];
            *(float4*)&a[0] = *(const float4*)&As[kk][ty * 8];
            *(float4*)&a[4] = *(const float4*)&As[kk][ty * 8 + 4];
            *(float4*)&b[0] = *(const float4*)&Bs[kk][tx * 8];
            *(float4*)&b[4] = *(const float4*)&Bs[kk][tx * 8 + 4];
#pragma unroll
            for (int i = 0; i < 8; i++)
#pragma unroll
                for (int j = 0; j < 8; j++)
                    acc[i][j] = fmaf(a[i], b[j], acc[i][j]);
        }
        __syncthreads();
    }
#pragma unroll
    for (int i = 0; i < 8; i++) {
        float* Cp = C + (size_t)(m0 + ty * 8 + i) * N + n0 + tx * 8;
        *(float4*)&Cp[0] = make_float4(acc[i][0], acc[i][1], acc[i][2], acc[i][3]);
        *(float4*)&Cp[4] = make_float4(acc[i][4], acc[i][5], acc[i][6], acc[i][7]);
    }
}

// One launch covers all three projections (grid.z selects input/weight).
__global__ __launch_bounds__(256) void proj3_kernel(
    const float* __restrict__ q_in, const float* __restrict__ k_in,
    const float* __restrict__ v_in, const float* __restrict__ wq,
    const float* __restrict__ wk,   const float* __restrict__ wv,
    float* __restrict__ qo, float* __restrict__ ko, float* __restrict__ vo) {
    if (blockIdx.z == 0)      gemm_nt_body(q_in, wq, qo);
    else if (blockIdx.z == 1) gemm_nt_body(k_in, wk, ko);
    else                      gemm_nt_body(v_in, wv, vo);
}

__global__ __launch_bounds__(256) void gemm_nt_kernel(const float* __restrict__ A,
                                                      const float* __restrict__ W,
                                                      float* __restrict__ C) {
    gemm_nt_body(A, W, C);
}

// ---------------------------------------------------------------------------
// Attention. One block = 64 query rows of one (b,h). Two sweeps over K/V:
//   sweep 1: online row max m and sum l (exact softmax statistics)
//   sweep 2: recompute S, write normalized attn tile to GMEM, accumulate ctx
// Shared: QT (swizzled, K-major), KT (swizzled, K-major; reused as P tile),
//         Vs (row-major). 3 * 16 KB = 48 KB static.
// Swizzle: phys_col = c ^ (4*(d&7))  -> conflict-free-ish stores, float4 reads.
// ---------------------------------------------------------------------------
__global__ __launch_bounds__(256) void attn_kernel(
    const float* __restrict__ Qg, const float* __restrict__ Kg,
    const float* __restrict__ Vg, float* __restrict__ Cg,
    float* __restrict__ attn_out) {

    __shared__ float QT[64 * 64];
    __shared__ float KT[64 * 64];   // reused as P tile in sweep 2
    __shared__ float Vs[64 * 64];

    const int t  = threadIdx.x;
    const int tx = t & 15, ty = t >> 4;
    const int q0 = blockIdx.x * 64;
    const int bh = blockIdx.y;               // 0..31
    const int b  = bh >> 4, h = bh & 15;

    const float* Qb = Qg + (size_t)b * L_ * D_ + h * 64;
    const float* Kb = Kg + (size_t)b * L_ * D_ + h * 64;
    const float* Vb = Vg + (size_t)b * L_ * D_ + h * 64;

    // Load Q tile transposed + swizzled: QT[d][q ^ swz(d)]
    for (int i = t; i < 4096; i += 256) {
        const int d = i & 63, q = i >> 6;
        QT[d * 64 + (q ^ ((d & 7) << 2))] = Qb[(size_t)(q0 + q) * D_ + d];
    }

    float m[4], l[4];
#pragma unroll
    for (int i = 0; i < 4; i++) { m[i] = -INFINITY; l[i] = 0.f; }

    // ---------------- Sweep 1: softmax statistics ----------------
    for (int k0 = 0; k0 < L_; k0 += 64) {
        __syncthreads();
        for (int i = t; i < 4096; i += 256) {
            const int d = i & 63, c = i >> 6;
            KT[d * 64 + (c ^ ((d & 7) << 2))] = Kb[(size_t)(k0 + c) * D_ + d];
        }
        __syncthreads();

        float s[4][4];
#pragma unroll
        for (int i = 0; i < 4; i++)
#pragma unroll
            for (int j = 0; j < 4; j++) s[i][j] = 0.f;

#pragma unroll 16
        for (int kk = 0; kk < 64; kk++) {
            const int e = (kk & 7) << 2;
            const float4 qa = *(const float4*)&QT[kk * 64 + ((ty * 4) ^ e)];
            const float4 kb = *(const float4*)&KT[kk * 64 + ((tx * 4) ^ e)];
            const float a[4] = {qa.x, qa.y, qa.z, qa.w};
            const float c[4] = {kb.x, kb.y, kb.z, kb.w};
#pragma unroll
            for (int i = 0; i < 4; i++)
#pragma unroll
                for (int j = 0; j < 4; j++)
                    s[i][j] = fmaf(a[i], c[j], s[i][j]);
        }

#pragma unroll
        for (int i = 0; i < 4; i++) {
#pragma unroll
            for (int j = 0; j < 4; j++) s[i][j] *= 0.125f;   // / sqrt(64)
            float mx = fmaxf(fmaxf(s[i][0], s[i][1]), fmaxf(s[i][2], s[i][3]));
#pragma unroll
            for (int o = 8; o >= 1; o >>= 1)
                mx = fmaxf(mx, __shfl_xor_sync(0xffffffffu, mx, o, 16));
            const float nm = fmaxf(m[i], mx);
            float ps = __expf(s[i][0] - nm) + __expf(s[i][1] - nm) +
                       __expf(s[i][2] - nm) + __expf(s[i][3] - nm);
#pragma unroll
            for (int o = 8; o >= 1; o >>= 1)
                ps += __shfl_xor_sync(0xffffffffu, ps, o, 16);
            l[i] = l[i] * __expf(m[i] - nm) + ps;
            m[i] = nm;
        }
    }

    float li[4];
#pragma unroll
    for (int i = 0; i < 4; i++) li[i] = 1.f / l[i];

    float cacc[4][4];
#pragma unroll
    for (int i = 0; i < 4; i++)
#pragma unroll
        for (int j = 0; j < 4; j++) cacc[i][j] = 0.f;

    // ---------------- Sweep 2: attn write + ctx ----------------
    for (int k0 = 0; k0 < L_; k0 += 64) {
        __syncthreads();
        for (int i = t; i < 4096; i += 256) {
            const int d = i & 63, c = i >> 6;
            KT[d * 64 + (c ^ ((d & 7) << 2))] = Kb[(size_t)(k0 + c) * D_ + d];
            Vs[c * 64 + d]                    = Vb[(size_t)(k0 + c) * D_ + d];
        }
        __syncthreads();

        float s[4][4];
#pragma unroll
        for (int i = 0; i < 4; i++)
#pragma unroll
            for (int j = 0; j < 4; j++) s[i][j] = 0.f;

#pragma unroll 16
        for (int kk = 0; kk < 64; kk++) {
            const int e = (kk & 7) << 2;
            const float4 qa = *(const float4*)&QT[kk * 64 + ((ty * 4) ^ e)];
            const float4 kb = *(const float4*)&KT[kk * 64 + ((tx * 4) ^ e)];
            const float a[4] = {qa.x, qa.y, qa.z, qa.w};
            const float c[4] = {kb.x, kb.y, kb.z, kb.w};
#pragma unroll
            for (int i = 0; i < 4; i++)
#pragma unroll
                for (int j = 0; j < 4; j++)
                    s[i][j] = fmaf(a[i], c[j], s[i][j]);
        }

        // normalized probabilities
#pragma unroll
        for (int i = 0; i < 4; i++)
#pragma unroll
            for (int j = 0; j < 4; j++)
                s[i][j] = __expf(s[i][j] * 0.125f - m[i]) * li[i];

        if (attn_out) {
#pragma unroll
            for (int i = 0; i < 4; i++) {
                const size_t row = (size_t)(bh * L_ + q0 + ty * 4 + i);
                *(float4*)&attn_out[row * L_ + k0 + tx * 4] =
                    make_float4(s[i][0], s[i][1], s[i][2], s[i][3]);
            }
        }

        __syncthreads();   // everyone done reading KT as K
#pragma unroll
        for (int i = 0; i < 4; i++)
            *(float4*)&KT[(ty * 4 + i) * 64 + tx * 4] =
                make_float4(s[i][0], s[i][1], s[i][2], s[i][3]);   // P tile
        __syncthreads();

#pragma unroll 16
        for (int c = 0; c < 64; c++) {
            float pv[4];
#pragma unroll
            for (int i = 0; i < 4; i++) pv[i] = KT[(ty * 4 + i) * 64 + c];
            const float4 vv = *(const float4*)&Vs[c * 64 + tx * 4];
            const float bv[4] = {vv.x, vv.y, vv.z, vv.w};
#pragma unroll
            for (int i = 0; i < 4; i++)
#pragma unroll
                for (int j = 0; j < 4; j++)
                    cacc[i][j] = fmaf(pv[i], bv[j], cacc[i][j]);
        }
    }

    // ctx -> merged-head layout [b*L + q][h*64 + d]
    float* Cb = Cg + (size_t)b * L_ * D_ + h * 64;
#pragma unroll
    for (int i = 0; i < 4; i++)
        *(float4*)&Cb[(size_t)(q0 + ty * 4 + i) * D_ + tx * 4] =
            make_float4(cacc[i][0], cacc[i][1], cacc[i][2], cacc[i][3]);
}

// ---------------------------------------------------------------------------
// Host launcher. Inputs (metadata order): key, value, query, wq, wk, wv, wo.
// Output: out [2,2048,1024] then attn [2,16,2048,2048] (tuple order).
// ---------------------------------------------------------------------------
extern "C" void kernel_launch(void* const* d_in, const int* in_sizes, int n_in,
                              void* d_out, int out_size) {
    const float* key   = (const float*)d_in[0];
    const float* value = (const float*)d_in[1];
    const float* query = (const float*)d_in[2];
    const float* wq    = (const float*)d_in[3];
    const float* wk    = (const float*)d_in[4];
    const float* wv    = (const float*)d_in[5];
    const float* wo    = (const float*)d_in[6];

    float *qb, *kb, *vb, *cb;
    cudaGetSymbolAddress((void**)&qb, g_Q);
    cudaGetSymbolAddress((void**)&kb, g_K);
    cudaGetSymbolAddress((void**)&vb, g_V);
    cudaGetSymbolAddress((void**)&cb, g_C);

    float* out  = (float*)d_out;
    float* attn = nullptr;
    const long long out_elems  = (long long)MT_ * D_;                 // 4194304
    const long long attn_elems = (long long)B_ * H_ * L_ * L_;        // 134217728
    if ((long long)out_size >= out_elems + attn_elems)
        attn = out + (size_t)out_elems;

    // Q/K/V projections (one launch, grid.z selects)
    proj3_kernel<<<dim3(32, 8, 3), 256>>>(query, key, value, wq, wk, wv,
                                          qb, kb, vb);
    // attention + attn output + ctx
    attn_kernel<<<dim3(32, 32), 256>>>(qb, kb, vb, cb, attn);
    // output projection straight into d_out
    gemm_nt_kernel<<<dim3(32, 8), 256>>>(cb, wo, out);
}

// round 2
// speedup vs baseline: 2.5618x; 2.5618x over previous
#include <cuda_runtime.h>
#include <math.h>
#include <stdint.h>

#define B_  2
#define L_  2048
#define D_  1024
#define H_  16
#define MT_ (B_ * L_)

// Scratch (allocation-free rule): 64 MB of __device__ globals.
__device__ float g_Q[(size_t)MT_ * D_];
__device__ float g_K[(size_t)MT_ * D_];
__device__ float g_V[(size_t)MT_ * D_];
__device__ float g_C[(size_t)MT_ * D_];

// ---------------------------------------------------------------------------
// helpers
// ---------------------------------------------------------------------------
__device__ __forceinline__ uint32_t s2u(const void* p) {
    return (uint32_t)__cvta_generic_to_shared(p);
}
__device__ __forceinline__ uint32_t f2tf(float f) {
    uint32_t u; asm("cvt.rna.tf32.f32 %0, %1;" : "=r"(u) : "f"(f)); return u;
}
__device__ __forceinline__ void ldsm4(uint32_t (&r)[4], uint32_t a) {
    asm volatile("ldmatrix.sync.aligned.m8n8.x4.shared.b16 {%0,%1,%2,%3}, [%4];"
                 : "=r"(r[0]), "=r"(r[1]), "=r"(r[2]), "=r"(r[3]) : "r"(a));
}
__device__ __forceinline__ void mma8(float (&d)[4], const uint32_t (&a)[4],
                                     uint32_t b0, uint32_t b1) {
    asm volatile(
        "mma.sync.aligned.m16n8k8.row.col.f32.tf32.tf32.f32 "
        "{%0,%1,%2,%3},{%4,%5,%6,%7},{%8,%9},{%0,%1,%2,%3};"
        : "+f"(d[0]), "+f"(d[1]), "+f"(d[2]), "+f"(d[3])
        : "r"(a[0]), "r"(a[1]), "r"(a[2]), "r"(a[3]), "r"(b0), "r"(b1));
}

// ---------------------------------------------------------------------------
// Tensor-core NT GEMM: C[M,1024] = A[M,1024] @ W[1024,1024]^T.
// 128x128 tile, BK=16, 256 threads (8 warps: 2m x 4n), warp tile 64x32.
// tf32 mma m16n8k8, ldmatrix feeds, register-prefetch pipeline.
// ---------------------------------------------------------------------------
__device__ __forceinline__ void gemm_tc_body(const float* __restrict__ A,
                                             const float* __restrict__ W,
                                             float* __restrict__ C) {
    __shared__ __align__(16) uint32_t As[128 * 20];
    __shared__ __align__(16) uint32_t Ws[128 * 20];
    const int t = threadIdx.x, lane = t & 31, warp = t >> 5;
    const int wm = warp & 1, wn = warp >> 1;
    const int m0 = blockIdx.x * 128, n0 = blockIdx.y * 128;

    float acc[4][4][4];
#pragma unroll
    for (int i = 0; i < 4; i++)
#pragma unroll
        for (int j = 0; j < 4; j++)
#pragma unroll
            for (int k = 0; k < 4; k++) acc[i][j][k] = 0.f;

    const int srow = t >> 1;            // 0..127
    const int sch0 = (t & 1) * 2;       // 0 or 2 (float4 chunks)
    const float4* A4 = (const float4*)A;
    const float4* W4 = (const float4*)W;

    float4 ra[2], rw[2];
#pragma unroll
    for (int j = 0; j < 2; j++) {
        ra[j] = A4[(size_t)(m0 + srow) * 256 + sch0 + j];
        rw[j] = W4[(size_t)(n0 + srow) * 256 + sch0 + j];
    }

    const uint32_t aB = s2u(As) +
        ((wm * 64 + (lane & 15)) * 20 + (lane >> 4) * 4) * 4;
    const uint32_t bB = s2u(Ws) +
        ((wn * 32 + (lane & 7) + ((lane >> 4) << 3)) * 20 + ((lane >> 3) & 1) * 4) * 4;

    for (int k0 = 0; k0 < 1024; k0 += 16) {
#pragma unroll
        for (int j = 0; j < 2; j++) {
            uint32_t* d = &As[srow * 20 + (sch0 + j) * 4];
            d[0] = f2tf(ra[j].x); d[1] = f2tf(ra[j].y);
            d[2] = f2tf(ra[j].z); d[3] = f2tf(ra[j].w);
            uint32_t* e = &Ws[srow * 20 + (sch0 + j) * 4];
            e[0] = f2tf(rw[j].x); e[1] = f2tf(rw[j].y);
            e[2] = f2tf(rw[j].z); e[3] = f2tf(rw[j].w);
        }
        __syncthreads();
        if (k0 + 16 < 1024) {
            const int kc = (k0 + 16) >> 2;
#pragma unroll
            for (int j = 0; j < 2; j++) {
                ra[j] = A4[(size_t)(m0 + srow) * 256 + kc + sch0 + j];
                rw[j] = W4[(size_t)(n0 + srow) * 256 + kc + sch0 + j];
            }
        }
#pragma unroll
        for (int ks = 0; ks < 2; ks++) {
            uint32_t af[4][4];
#pragma unroll
            for (int mt = 0; mt < 4; mt++) ldsm4(af[mt], aB + mt * 1280 + ks * 32);
            uint32_t bf[2][4];
#pragma unroll
            for (int p = 0; p < 2; p++) ldsm4(bf[p], bB + p * 1280 + ks * 32);
#pragma unroll
            for (int mt = 0; mt < 4; mt++)
#pragma unroll
                for (int p = 0; p < 2; p++) {
                    mma8(acc[mt][2 * p],     af[mt], bf[p][0], bf[p][1]);
                    mma8(acc[mt][2 * p + 1], af[mt], bf[p][2], bf[p][3]);
                }
        }
        __syncthreads();
    }
#pragma unroll
    for (int mt = 0; mt < 4; mt++) {
        const int row = m0 + wm * 64 + mt * 16 + (lane >> 2);
#pragma unroll
        for (int nt = 0; nt < 4; nt++) {
            const int col = n0 + wn * 32 + nt * 8 + (lane & 3) * 2;
            *(float2*)&C[(size_t)row * 1024 + col] =
                make_float2(acc[mt][nt][0], acc[mt][nt][1]);
            *(float2*)&C[(size_t)(row + 8) * 1024 + col] =
                make_float2(acc[mt][nt][2], acc[mt][nt][3]);
        }
    }
}

__global__ __launch_bounds__(256) void proj3_kernel(
    const float* __restrict__ q_in, const float* __restrict__ k_in,
    const float* __restrict__ v_in, const float* __restrict__ wq,
    const float* __restrict__ wk,   const float* __restrict__ wv,
    float* __restrict__ qo, float* __restrict__ ko, float* __restrict__ vo) {
    if (blockIdx.z == 0)      gemm_tc_body(q_in, wq, qo);
    else if (blockIdx.z == 1) gemm_tc_body(k_in, wk, ko);
    else                      gemm_tc_body(v_in, wv, vo);
}

__global__ __launch_bounds__(256) void gemm_tc_kernel(const float* __restrict__ A,
                                                      const float* __restrict__ W,
                                                      float* __restrict__ C) {
    gemm_tc_body(A, W, C);
}

// ---------------------------------------------------------------------------
// Attention (tensor core). Block = 64 q-rows of one (b,h), 128 threads
// (4 warps, each owns 16 q-rows). Two sweeps over 64-col K tiles:
//   sweep 1: online softmax stats (m, l) from S = Q*K^T (Q pre-scaled 1/8)
//   sweep 2: recompute S, write normalized attn to gmem, P@V into ctx acc.
// Dynamic smem: Qs[64][68] | Ks[64][68] (aliased by P tile) | Vs(d-major)[64][68]
// all tf32 bits. 52224 bytes.
// ---------------------------------------------------------------------------
__global__ __launch_bounds__(128) void attn_tc_kernel(
    const float* __restrict__ Qg, const float* __restrict__ Kg,
    const float* __restrict__ Vg, float* __restrict__ Cg,
    float* __restrict__ attn_out) {

    extern __shared__ __align__(16) uint32_t sm[];
    uint32_t* Qs = sm;               // 64*68
    uint32_t* Ks = sm + 64 * 68;     // 64*68 (re-used as P tile in sweep 2)
    uint32_t* Vs = sm + 2 * 64 * 68; // 64*68, layout [d][kc]

    const int t = threadIdx.x, lane = t & 31, warp = t >> 5;
    const int q0 = blockIdx.x * 64;
    const int bh = blockIdx.y;
    const int b = bh >> 4, h = bh & 15;

    const float* Qb = Qg + (size_t)b * L_ * D_ + h * 64;
    const float* Kb = Kg + (size_t)b * L_ * D_ + h * 64;
    const float* Vb = Vg + (size_t)b * L_ * D_ + h * 64;

    // Load Q tile, pre-scaled by 1/sqrt(dk)=0.125 (exact power of 2).
#pragma unroll
    for (int j = 0; j < 8; j++) {
        const int fid = t + j * 128;
        const int row = fid >> 4, ch = fid & 15;
        const float4 v = ((const float4*)(Qb + (size_t)(q0 + row) * D_))[ch];
        uint32_t* d = &Qs[row * 68 + ch * 4];
        d[0] = f2tf(v.x * 0.125f); d[1] = f2tf(v.y * 0.125f);
        d[2] = f2tf(v.z * 0.125f); d[3] = f2tf(v.w * 0.125f);
    }

    const uint32_t qB = s2u(Qs) + ((warp * 16 + (lane & 15)) * 68 + (lane >> 4) * 4) * 4;
    const uint32_t kB = s2u(Ks) +
        (((lane & 7) + ((lane >> 4) << 3)) * 68 + ((lane >> 3) & 1) * 4) * 4;
    const uint32_t vB = s2u(Vs) +
        (((lane & 7) + ((lane >> 4) << 3)) * 68 + ((lane >> 3) & 1) * 4) * 4;
    const uint32_t pB = s2u(Ks) + ((warp * 16 + (lane & 15)) * 68 + (lane >> 4) * 4) * 4;

    float m2[2] = {-INFINITY, -INFINITY}, l2[2] = {0.f, 0.f};

    // ---------------- Sweep 1: softmax statistics ----------------
    for (int k0 = 0; k0 < L_; k0 += 64) {
        __syncthreads();
#pragma unroll
        for (int j = 0; j < 8; j++) {
            const int fid = t + j * 128;
            const int row = fid >> 4, ch = fid & 15;
            const float4 v = ((const float4*)(Kb + (size_t)(k0 + row) * D_))[ch];
            uint32_t* d = &Ks[row * 68 + ch * 4];
            d[0] = f2tf(v.x); d[1] = f2tf(v.y); d[2] = f2tf(v.z); d[3] = f2tf(v.w);
        }
        __syncthreads();

        float s[8][4];
#pragma unroll
        for (int nt = 0; nt < 8; nt++)
#pragma unroll
            for (int i = 0; i < 4; i++) s[nt][i] = 0.f;

#pragma unroll
        for (int ks = 0; ks < 8; ks++) {
            uint32_t af[4];
            ldsm4(af, qB + ks * 32);
#pragma unroll
            for (int p = 0; p < 4; p++) {
                uint32_t bf[4];
                ldsm4(bf, kB + p * 4352 + ks * 32);   // 16*68*4 = 4352
                mma8(s[2 * p],     af, bf[0], bf[1]);
                mma8(s[2 * p + 1], af, bf[2], bf[3]);
            }
        }
#pragma unroll
        for (int r = 0; r < 2; r++) {
            float mx = -INFINITY;
#pragma unroll
            for (int nt = 0; nt < 8; nt++)
                mx = fmaxf(mx, fmaxf(s[nt][2 * r], s[nt][2 * r + 1]));
            mx = fmaxf(mx, __shfl_xor_sync(0xffffffffu, mx, 1));
            mx = fmaxf(mx, __shfl_xor_sync(0xffffffffu, mx, 2));
            const float nm = fmaxf(m2[r], mx);
            float ps = 0.f;
#pragma unroll
            for (int nt = 0; nt < 8; nt++)
                ps += __expf(s[nt][2 * r] - nm) + __expf(s[nt][2 * r + 1] - nm);
            ps += __shfl_xor_sync(0xffffffffu, ps, 1);
            ps += __shfl_xor_sync(0xffffffffu, ps, 2);
            l2[r] = l2[r] * __expf(m2[r] - nm) + ps;
            m2[r] = nm;
        }
    }

    const float il[2] = {1.f / l2[0], 1.f / l2[1]};

    float o[8][4];
#pragma unroll
    for (int nt = 0; nt < 8; nt++)
#pragma unroll
        for (int i = 0; i < 4; i++) o[nt][i] = 0.f;

    // ---------------- Sweep 2: attn write + P@V ----------------
    for (int k0 = 0; k0 < L_; k0 += 64) {
        __syncthreads();
#pragma unroll
        for (int j = 0; j < 8; j++) {
            const int fid = t + j * 128;
            const int row = fid >> 4, ch = fid & 15;
            const float4 kv = ((const float4*)(Kb + (size_t)(k0 + row) * D_))[ch];
            uint32_t* d = &Ks[row * 68 + ch * 4];
            d[0] = f2tf(kv.x); d[1] = f2tf(kv.y); d[2] = f2tf(kv.z); d[3] = f2tf(kv.w);
            const float4 vv = ((const float4*)(Vb + (size_t)(k0 + row) * D_))[ch];
            Vs[(ch * 4 + 0) * 68 + row] = f2tf(vv.x);
            Vs[(ch * 4 + 1) * 68 + row] = f2tf(vv.y);
            Vs[(ch * 4 + 2) * 68 + row] = f2tf(vv.z);
            Vs[(ch * 4 + 3) * 68 + row] = f2tf(vv.w);
        }
        __syncthreads();

        float s[8][4];
#pragma unroll
        for (int nt = 0; nt < 8; nt++)
#pragma unroll
            for (int i = 0; i < 4; i++) s[nt][i] = 0.f;

#pragma unroll
        for (int ks = 0; ks < 8; ks++) {
            uint32_t af[4];
            ldsm4(af, qB + ks * 32);
#pragma unroll
            for (int p = 0; p < 4; p++) {
                uint32_t bf[4];
                ldsm4(bf, kB + p * 4352 + ks * 32);
                mma8(s[2 * p],     af, bf[0], bf[1]);
                mma8(s[2 * p + 1], af, bf[2], bf[3]);
            }
        }

        // normalized probabilities (exact: l accumulated with the same S values)
#pragma unroll
        for (int nt = 0; nt < 8; nt++) {
            s[nt][0] = __expf(s[nt][0] - m2[0]) * il[0];
            s[nt][1] = __expf(s[nt][1] - m2[0]) * il[0];
            s[nt][2] = __expf(s[nt][2] - m2[1]) * il[1];
            s[nt][3] = __expf(s[nt][3] - m2[1]) * il[1];
        }

        if (attn_out) {
            const size_t r0 = (size_t)(bh * L_ + q0 + warp * 16 + (lane >> 2));
            const int cc = k0 + (lane & 3) * 2;
#pragma unroll
            for (int nt = 0; nt < 8; nt++) {
                *(float2*)&attn_out[r0 * L_ + cc + nt * 8] =
                    make_float2(s[nt][0], s[nt][1]);
                *(float2*)&attn_out[(r0 + 8) * L_ + cc + nt * 8] =
                    make_float2(s[nt][2], s[nt][3]);
            }
        }

        __syncthreads();   // all warps done reading Ks as K
        {
            const int pr = warp * 16 + (lane >> 2);
            const int pc = (lane & 3) * 2;
#pragma unroll
            for (int nt = 0; nt < 8; nt++) {
                Ks[pr * 68 + pc + nt * 8]           = f2tf(s[nt][0]);
                Ks[pr * 68 + pc + nt * 8 + 1]       = f2tf(s[nt][1]);
                Ks[(pr + 8) * 68 + pc + nt * 8]     = f2tf(s[nt][2]);
                Ks[(pr + 8) * 68 + pc + nt * 8 + 1] = f2tf(s[nt][3]);
            }
        }
        __syncthreads();

#pragma unroll
        for (int ks = 0; ks < 8; ks++) {
            uint32_t af[4];
            ldsm4(af, pB + ks * 32);
#pragma unroll
            for (int p = 0; p < 4; p++) {
                uint32_t bf[4];
                ldsm4(bf, vB + p * 4352 + ks * 32);
                mma8(o[2 * p],     af, bf[0], bf[1]);
                mma8(o[2 * p + 1], af, bf[2], bf[3]);
            }
        }
    }

    // ctx -> merged-head layout
    float* Cb = Cg + (size_t)b * L_ * D_ + h * 64;
    const int row = q0 + warp * 16 + (lane >> 2);
#pragma unroll
    for (int nt = 0; nt < 8; nt++) {
        const int col = nt * 8 + (lane & 3) * 2;
        *(float2*)&Cb[(size_t)row * D_ + col]       = make_float2(o[nt][0], o[nt][1]);
        *(float2*)&Cb[(size_t)(row + 8) * D_ + col] = make_float2(o[nt][2], o[nt][3]);
    }
}

// ---------------------------------------------------------------------------
// Host launcher. Inputs: key, value, query, wq, wk, wv, wo.
// Output buffer: out [2,2048,1024] then attn [2,16,2048,2048].
// ---------------------------------------------------------------------------
extern "C" void kernel_launch(void* const* d_in, const int* in_sizes, int n_in,
                              void* d_out, int out_size) {
    const float* key   = (const float*)d_in[0];
    const float* value = (const float*)d_in[1];
    const float* query = (const float*)d_in[2];
    const float* wq    = (const float*)d_in[3];
    const float* wk    = (const float*)d_in[4];
    const float* wv    = (const float*)d_in[5];
    const float* wo    = (const float*)d_in[6];

    float *qb, *kb, *vb, *cb;
    cudaGetSymbolAddress((void**)&qb, g_Q);
    cudaGetSymbolAddress((void**)&kb, g_K);
    cudaGetSymbolAddress((void**)&vb, g_V);
    cudaGetSymbolAddress((void**)&cb, g_C);

    float* out  = (float*)d_out;
    float* attn = nullptr;
    const long long out_elems  = (long long)MT_ * D_;
    const long long attn_elems = (long long)B_ * H_ * L_ * L_;
    if ((long long)out_size >= out_elems + attn_elems)
        attn = out + (size_t)out_elems;

    static int smem_set = 0;
    (void)smem_set;
    cudaFuncSetAttribute(attn_tc_kernel,
                         cudaFuncAttributeMaxDynamicSharedMemorySize, 52224);

    proj3_kernel<<<dim3(32, 8, 3), 256>>>(query, key, value, wq, wk, wv,
                                          qb, kb, vb);
    attn_tc_kernel<<<dim3(32, 32), 128, 52224>>>(qb, kb, vb, cb, attn);
    gemm_tc_kernel<<<dim3(32, 8), 256>>>(cb, wo, out);
}

// round 4
// speedup vs baseline: 3.0400x; 1.1867x over previous
#include <cuda_runtime.h>
#include <math.h>
#include <stdint.h>

#define B_  2
#define L_  2048
#define D_  1024
#define H_  16
#define MT_ (B_ * L_)

// tf32 scratch (allocation-free rule): __device__ globals, 16B aligned for cp.async.
__device__ __align__(256) uint32_t g_Xt[3][(size_t)MT_ * D_];  // query,key,value (tf32)
__device__ __align__(256) uint32_t g_Wt[4][(size_t)D_ * D_];   // wq,wk,wv,wo (tf32)
__device__ __align__(256) uint32_t g_Qt[(size_t)MT_ * D_];     // Q*0.125 (tf32)
__device__ __align__(256) uint32_t g_Kt[(size_t)MT_ * D_];
__device__ __align__(256) uint32_t g_Vt[(size_t)MT_ * D_];
__device__ __align__(256) uint32_t g_Ct[(size_t)MT_ * D_];     // ctx (tf32)

// ---------------------------------------------------------------------------
// helpers
// ---------------------------------------------------------------------------
__device__ __forceinline__ uint32_t s2u(const void* p) {
    return (uint32_t)__cvta_generic_to_shared(p);
}
__device__ __forceinline__ uint32_t f2tf(float f) {
    uint32_t u; asm("cvt.rna.tf32.f32 %0, %1;" : "=r"(u) : "f"(f)); return u;
}
__device__ __forceinline__ void ldsm4(uint32_t (&r)[4], uint32_t a) {
    asm volatile("ldmatrix.sync.aligned.m8n8.x4.shared.b16 {%0,%1,%2,%3}, [%4];"
                 : "=r"(r[0]), "=r"(r[1]), "=r"(r[2]), "=r"(r[3]) : "r"(a));
}
__device__ __forceinline__ void mma8(float (&d)[4], const uint32_t (&a)[4],
                                     uint32_t b0, uint32_t b1) {
    asm volatile(
        "mma.sync.aligned.m16n8k8.row.col.f32.tf32.tf32.f32 "
        "{%0,%1,%2,%3},{%4,%5,%6,%7},{%8,%9},{%0,%1,%2,%3};"
        : "+f"(d[0]), "+f"(d[1]), "+f"(d[2]), "+f"(d[3])
        : "r"(a[0]), "r"(a[1]), "r"(a[2]), "r"(a[3]), "r"(b0), "r"(b1));
}
__device__ __forceinline__ void cpa16(uint32_t dst, const void* src) {
    asm volatile("cp.async.cg.shared.global [%0], [%1], 16;" :: "r"(dst), "l"(src));
}
#define CP_COMMIT() asm volatile("cp.async.commit_group;")
#define CP_WAIT(n)  asm volatile("cp.async.wait_group %0;" :: "n"(n))

// ---------------------------------------------------------------------------
// fp32 -> tf32 bulk convert (7 segments: 3 inputs of 4M, 4 weights of 1M)
// ---------------------------------------------------------------------------
__global__ __launch_bounds__(256) void cvt_kernel(
    const float* q, const float* k, const float* v, const float* wq,
    const float* wk, const float* wv, const float* wo) {
    const float* srcs[7] = {q, k, v, wq, wk, wv, wo};
    uint32_t* dsts[7] = {g_Xt[0], g_Xt[1], g_Xt[2],
                         g_Wt[0], g_Wt[1], g_Wt[2], g_Wt[3]};
    const int seg = blockIdx.y;
    const float4* s4 = (const float4*)srcs[seg];
    uint4* d4 = (uint4*)dsts[seg];
    const int n4 = (seg < 3 ? MT_ * D_ : D_ * D_) / 4;
    for (int i = blockIdx.x * 256 + threadIdx.x; i < n4; i += gridDim.x * 256) {
        const float4 val = s4[i];
        uint4 o;
        o.x = f2tf(val.x); o.y = f2tf(val.y); o.z = f2tf(val.z); o.w = f2tf(val.w);
        d4[i] = o;
    }
}

// ---------------------------------------------------------------------------
// tf32-in tensor-core NT GEMM: C[M,1024] = A @ W^T. 128x128 tile, BK=16,
// 256 threads (8 warps 2m x 4n, warp tile 64x32), cp.async double buffer.
// ---------------------------------------------------------------------------
template <bool TF32OUT>
__device__ __forceinline__ void gemm_tc_body(const uint32_t* __restrict__ A,
                                             const uint32_t* __restrict__ W,
                                             void* __restrict__ Cout, float scale) {
    __shared__ __align__(16) uint32_t As[2 * 2560];   // 2 stages, 128 rows x 20
    __shared__ __align__(16) uint32_t Ws[2 * 2560];
    const int t = threadIdx.x, lane = t & 31, warp = t >> 5;
    const int wm = warp & 1, wn = warp >> 1;
    const int m0 = blockIdx.x * 128, n0 = blockIdx.y * 128;

    float acc[4][4][4];
#pragma unroll
    for (int i = 0; i < 4; i++)
#pragma unroll
        for (int j = 0; j < 4; j++)
#pragma unroll
            for (int k = 0; k < 4; k++) acc[i][j][k] = 0.f;

    const int lrow = t >> 2, lcc = (t & 3) * 4;   // rows 0..63, word chunk
    const uint32_t aS = s2u(As), wS = s2u(Ws);

    // preload stage 0
    {
        const uint32_t da = aS + (lrow * 20 + lcc) * 4;
        cpa16(da,                A + (size_t)(m0 + lrow) * 1024 + lcc);
        cpa16(da + 64 * 80,      A + (size_t)(m0 + lrow + 64) * 1024 + lcc);
        const uint32_t db = wS + (lrow * 20 + lcc) * 4;
        cpa16(db,                W + (size_t)(n0 + lrow) * 1024 + lcc);
        cpa16(db + 64 * 80,      W + (size_t)(n0 + lrow + 64) * 1024 + lcc);
        CP_COMMIT();
    }

    const uint32_t aB0 = aS + ((wm * 64 + (lane & 15)) * 20 + (lane >> 4) * 4) * 4;
    const uint32_t bB0 = wS +
        ((wn * 32 + (lane & 7) + ((lane >> 4) << 3)) * 20 + ((lane >> 3) & 1) * 4) * 4;

    for (int kt = 0; kt < 64; kt++) {
        const int buf = kt & 1;
        if (kt + 1 < 64) {
            const int kw = (kt + 1) * 16;
            const uint32_t so = (buf ^ 1) * 10240;
            const uint32_t da = aS + so + (lrow * 20 + lcc) * 4;
            cpa16(da,           A + (size_t)(m0 + lrow) * 1024 + kw + lcc);
            cpa16(da + 64 * 80, A + (size_t)(m0 + lrow + 64) * 1024 + kw + lcc);
            const uint32_t db = wS + so + (lrow * 20 + lcc) * 4;
            cpa16(db,           W + (size_t)(n0 + lrow) * 1024 + kw + lcc);
            cpa16(db + 64 * 80, W + (size_t)(n0 + lrow + 64) * 1024 + kw + lcc);
            CP_COMMIT();
            CP_WAIT(1);
        } else {
            CP_WAIT(0);
        }
        __syncthreads();

        const uint32_t aB = aB0 + buf * 10240;
        const uint32_t bB = bB0 + buf * 10240;
#pragma unroll
        for (int ks = 0; ks < 2; ks++) {
            uint32_t af[4][4];
#pragma unroll
            for (int mt = 0; mt < 4; mt++) ldsm4(af[mt], aB + mt * 1280 + ks * 32);
            uint32_t bf[2][4];
#pragma unroll
            for (int p = 0; p < 2; p++) ldsm4(bf[p], bB + p * 1280 + ks * 32);
#pragma unroll
            for (int mt = 0; mt < 4; mt++)
#pragma unroll
                for (int p = 0; p < 2; p++) {
                    mma8(acc[mt][2 * p],     af[mt], bf[p][0], bf[p][1]);
                    mma8(acc[mt][2 * p + 1], af[mt], bf[p][2], bf[p][3]);
                }
        }
        __syncthreads();
    }

#pragma unroll
    for (int mt = 0; mt < 4; mt++) {
        const int row = m0 + wm * 64 + mt * 16 + (lane >> 2);
#pragma unroll
        for (int nt = 0; nt < 4; nt++) {
            const int col = n0 + wn * 32 + nt * 8 + (lane & 3) * 2;
            if (TF32OUT) {
                uint32_t* C = (uint32_t*)Cout;
                uint2 v0 = make_uint2(f2tf(acc[mt][nt][0] * scale),
                                      f2tf(acc[mt][nt][1] * scale));
                uint2 v1 = make_uint2(f2tf(acc[mt][nt][2] * scale),
                                      f2tf(acc[mt][nt][3] * scale));
                *(uint2*)&C[(size_t)row * 1024 + col] = v0;
                *(uint2*)&C[(size_t)(row + 8) * 1024 + col] = v1;
            } else {
                float* C = (float*)Cout;
                *(float2*)&C[(size_t)row * 1024 + col] =
                    make_float2(acc[mt][nt][0], acc[mt][nt][1]);
                *(float2*)&C[(size_t)(row + 8) * 1024 + col] =
                    make_float2(acc[mt][nt][2], acc[mt][nt][3]);
            }
        }
    }
}

__global__ __launch_bounds__(256, 2) void proj3_kernel() {
    const int z = blockIdx.z;
    if (z == 0)      gemm_tc_body<true>(g_Xt[0], g_Wt[0], g_Qt, 0.125f);
    else if (z == 1) gemm_tc_body<true>(g_Xt[1], g_Wt[1], g_Kt, 1.f);
    else             gemm_tc_body<true>(g_Xt[2], g_Wt[2], g_Vt, 1.f);
}

__global__ __launch_bounds__(256, 2) void outproj_kernel(float* __restrict__ out) {
    gemm_tc_body<false>(g_Ct, g_Wt[3], out, 1.f);
}

// ---------------------------------------------------------------------------
// Attention v2: block = 128 q-rows of one (b,h), 256 threads (8 warps x 16 rows,
// warp-private). tf32 Q/K/V via cp.async. Two sweeps (stats; attn-write + P@V).
// smem words: Qs 128x68 | Ks 64x68 | Vs 64x72 (row-major) | Ps 128x68
// ---------------------------------------------------------------------------
#define SM_QS 0
#define SM_KS 8704
#define SM_VS (8704 + 4352)
#define SM_PS (8704 + 4352 + 4608)
#define SM_WORDS (8704 + 4352 + 4608 + 8704)   // 26368 words = 105472 B

__global__ __launch_bounds__(256, 2) void attn_tc_kernel(float* __restrict__ attn_out) {
    extern __shared__ __align__(16) uint32_t sm[];
    uint32_t* Vs = sm + SM_VS;

    const int t = threadIdx.x, lane = t & 31, warp = t >> 5;
    const int q0 = blockIdx.x * 128;
    const int bh = blockIdx.y;
    const int b = bh >> 4, h = bh & 15;

    const uint32_t* Qb = g_Qt + (size_t)b * L_ * D_ + h * 64;
    const uint32_t* Kb = g_Kt + (size_t)b * L_ * D_ + h * 64;
    const uint32_t* Vb = g_Vt + (size_t)b * L_ * D_ + h * 64;

    const uint32_t smS = s2u(sm);
    const int lrow = t >> 4, lcc = (t & 15) * 4;   // 16 chunks per 64-word row

    // Q tile: 128 rows (already scaled by 1/8)
#pragma unroll
    for (int j = 0; j < 8; j++) {
        const int row = lrow + j * 16;
        cpa16(smS + (SM_QS + row * 68 + lcc) * 4, Qb + (size_t)(q0 + row) * D_ + lcc);
    }
    CP_COMMIT();

    const uint32_t qB = smS + (SM_QS + (warp * 16 + (lane & 15)) * 68 + (lane >> 4) * 4) * 4;
    const uint32_t kB = smS + (SM_KS + ((lane & 7) + ((lane >> 4) << 3)) * 68 +
                               ((lane >> 3) & 1) * 4) * 4;
    const uint32_t pB = smS + (SM_PS + (warp * 16 + (lane & 15)) * 68 + (lane >> 4) * 4) * 4;

    float m2[2] = {-INFINITY, -INFINITY}, l2[2] = {0.f, 0.f};

    // ---------------- Sweep 1: softmax statistics ----------------
    for (int k0 = 0; k0 < L_; k0 += 64) {
        __syncthreads();
#pragma unroll
        for (int j = 0; j < 4; j++) {
            const int row = lrow + j * 16;
            cpa16(smS + (SM_KS + row * 68 + lcc) * 4, Kb + (size_t)(k0 + row) * D_ + lcc);
        }
        CP_COMMIT(); CP_WAIT(0);
        __syncthreads();

        float s[8][4];
#pragma unroll
        for (int nt = 0; nt < 8; nt++)
#pragma unroll
            for (int i = 0; i < 4; i++) s[nt][i] = 0.f;

#pragma unroll
        for (int ks = 0; ks < 8; ks++) {
            uint32_t af[4];
            ldsm4(af, qB + ks * 32);
#pragma unroll
            for (int p = 0; p < 4; p++) {
                uint32_t bf[4];
                ldsm4(bf, kB + p * 4352 + ks * 32);   // 16 rows * 68 w * 4 B = 4352 B
                mma8(s[2 * p],     af, bf[0], bf[1]);
                mma8(s[2 * p + 1], af, bf[2], bf[3]);
            }
        }
#pragma unroll
        for (int r = 0; r < 2; r++) {
            float mx = -INFINITY;
#pragma unroll
            for (int nt = 0; nt < 8; nt++)
                mx = fmaxf(mx, fmaxf(s[nt][2 * r], s[nt][2 * r + 1]));
            mx = fmaxf(mx, __shfl_xor_sync(0xffffffffu, mx, 1));
            mx = fmaxf(mx, __shfl_xor_sync(0xffffffffu, mx, 2));
            const float nm = fmaxf(m2[r], mx);
            float ps = 0.f;
#pragma unroll
            for (int nt = 0; nt < 8; nt++)
                ps += __expf(s[nt][2 * r] - nm) + __expf(s[nt][2 * r + 1] - nm);
            ps += __shfl_xor_sync(0xffffffffu, ps, 1);
            ps += __shfl_xor_sync(0xffffffffu, ps, 2);
            l2[r] = l2[r] * __expf(m2[r] - nm) + ps;
            m2[r] = nm;
        }
    }

    const float il[2] = {1.f / l2[0], 1.f / l2[1]};

    float o[8][4];
#pragma unroll
    for (int nt = 0; nt < 8; nt++)
#pragma unroll
        for (int i = 0; i < 4; i++) o[nt][i] = 0.f;

    // ---------------- Sweep 2: attn write + P@V ----------------
    for (int k0 = 0; k0 < L_; k0 += 64) {
        __syncthreads();
#pragma unroll
        for (int j = 0; j < 4; j++) {
            const int row = lrow + j * 16;
            cpa16(smS + (SM_KS + row * 68 + lcc) * 4, Kb + (size_t)(k0 + row) * D_ + lcc);
            cpa16(smS + (SM_VS + row * 72 + lcc) * 4, Vb + (size_t)(k0 + row) * D_ + lcc);
        }
        CP_COMMIT(); CP_WAIT(0);
        __syncthreads();

        float s[8][4];
#pragma unroll
        for (int nt = 0; nt < 8; nt++)
#pragma unroll
            for (int i = 0; i < 4; i++) s[nt][i] = 0.f;

#pragma unroll
        for (int ks = 0; ks < 8; ks++) {
            uint32_t af[4];
            ldsm4(af, qB + ks * 32);
#pragma unroll
            for (int p = 0; p < 4; p++) {
                uint32_t bf[4];
                ldsm4(bf, kB + p * 4352 + ks * 32);
                mma8(s[2 * p],     af, bf[0], bf[1]);
                mma8(s[2 * p + 1], af, bf[2], bf[3]);
            }
        }

#pragma unroll
        for (int nt = 0; nt < 8; nt++) {
            s[nt][0] = __expf(s[nt][0] - m2[0]) * il[0];
            s[nt][1] = __expf(s[nt][1] - m2[0]) * il[0];
            s[nt][2] = __expf(s[nt][2] - m2[1]) * il[1];
            s[nt][3] = __expf(s[nt][3] - m2[1]) * il[1];
        }

        if (attn_out) {
            const size_t r0 = (size_t)(bh * L_ + q0 + warp * 16 + (lane >> 2));
            const int cc = k0 + (lane & 3) * 2;
#pragma unroll
            for (int nt = 0; nt < 8; nt++) {
                *(float2*)&attn_out[r0 * L_ + cc + nt * 8] =
                    make_float2(s[nt][0], s[nt][1]);
                *(float2*)&attn_out[(r0 + 8) * L_ + cc + nt * 8] =
                    make_float2(s[nt][2], s[nt][3]);
            }
        }

        // P tile (warp-private rows) -> smem as tf32
        {
            const int pr = warp * 16 + (lane >> 2);
            const int pc = (lane & 3) * 2;
            uint32_t* P0 = sm + SM_PS + pr * 68 + pc;
            uint32_t* P1 = sm + SM_PS + (pr + 8) * 68 + pc;
#pragma unroll
            for (int nt = 0; nt < 8; nt++) {
                *(uint2*)&P0[nt * 8] = make_uint2(f2tf(s[nt][0]), f2tf(s[nt][1]));
                *(uint2*)&P1[nt * 8] = make_uint2(f2tf(s[nt][2]), f2tf(s[nt][3]));
            }
        }
        __syncwarp();

        // O += P @ V  (V row-major, B frags via direct LDS)
#pragma unroll
        for (int ks = 0; ks < 8; ks++) {
            uint32_t af[4];
            ldsm4(af, pB + ks * 32);
            const int kr = ks * 8 + (lane & 3);
            const int dn = (lane >> 2);
#pragma unroll
            for (int nt = 0; nt < 8; nt++) {
                const uint32_t b0 = Vs[kr * 72 + nt * 8 + dn];
                const uint32_t b1 = Vs[(kr + 4) * 72 + nt * 8 + dn];
                mma8(o[nt], af, b0, b1);
            }
        }
    }

    // ctx (tf32) -> merged-head layout
    {
        const int r = q0 + warp * 16 + (lane >> 2);
        uint32_t* C0 = g_Ct + ((size_t)b * L_ + r) * D_ + h * 64 + (lane & 3) * 2;
        uint32_t* C1 = g_Ct + ((size_t)b * L_ + r + 8) * D_ + h * 64 + (lane & 3) * 2;
#pragma unroll
        for (int nt = 0; nt < 8; nt++) {
            *(uint2*)&C0[nt * 8] = make_uint2(f2tf(o[nt][0]), f2tf(o[nt][1]));
            *(uint2*)&C1[nt * 8] = make_uint2(f2tf(o[nt][2]), f2tf(o[nt][3]));
        }
    }
}

// ---------------------------------------------------------------------------
// Host launcher. Inputs: key, value, query, wq, wk, wv, wo.
// Output: out [2,2048,1024] then attn [2,16,2048,2048].
// ---------------------------------------------------------------------------
extern "C" void kernel_launch(void* const* d_in, const int* in_sizes, int n_in,
                              void* d_out, int out_size) {
    const float* key   = (const float*)d_in[0];
    const float* value = (const float*)d_in[1];
    const float* query = (const float*)d_in[2];
    const float* wq    = (const float*)d_in[3];
    const float* wk    = (const float*)d_in[4];
    const float* wv    = (const float*)d_in[5];
    const float* wo    = (const float*)d_in[6];

    float* out  = (float*)d_out;
    float* attn = nullptr;
    const long long out_elems  = (long long)MT_ * D_;
    const long long attn_elems = (long long)B_ * H_ * L_ * L_;
    if ((long long)out_size >= out_elems + attn_elems)
        attn = out + (size_t)out_elems;

    cudaFuncSetAttribute(attn_tc_kernel,
                         cudaFuncAttributeMaxDynamicSharedMemorySize,
                         SM_WORDS * 4);

    cvt_kernel<<<dim3(128, 7), 256>>>(query, key, value, wq, wk, wv, wo);
    proj3_kernel<<<dim3(32, 8, 3), 256>>>();
    attn_tc_kernel<<<dim3(16, 32), 256, SM_WORDS * 4>>>(attn);
    outproj_kernel<<<dim3(32, 8), 256>>>(out);
}